// round 14
// baseline (speedup 1.0000x reference)
#include <cuda_runtime.h>
#include <cstdint>

#define E 128
#define F 32

// smem layout (dynamic, bytes):
//   C0s : 16384 floats      [0, 65536)
//   ksf : 32*132 floats     [65536, 82432)   (raw keys, transposed, stride 132)
//   cp  : 32*32 uint2       [82432, 90624)   (pre-scaled col byte offsets, 16b packed)
//   rpq : 32*33 uint2       [90624, 99072)   (row byte offsets, [f][w] = {pair_w, pair_63-w})
//   cnt : 1 u32             [99072, 99076)   (round-B ranks-done counter)
// After phase 2 the front region is reused as the staging tile
//   T   : 128*129 floats    [0, 66048)
#define SMEM_C0     0
#define SMEM_KS     65536
#define SMEM_CP     82432
#define SMEM_RP     90624
#define SMEM_CNT    99072
#define SMEM_TOTAL  99076

// ---------------------------------------------------------------------------
// Compile-time fixed table C0[a,b] = (W0^2)[a,b] - s0[a]*s0[b]/(E-1),
// W0[a,b] = 1/(|a-b|+1). Persymmetry quarters the constexpr work.
// ---------------------------------------------------------------------------
struct C0Table { float v[E * E]; };

static constexpr C0Table make_c0() {
    C0Table t{};
    double inv[E] = {};
    for (int i = 0; i < E; ++i) inv[i] = 1.0 / (double)(i + 1);
    double s0[E] = {};
    for (int b = 0; b < E; ++b) {
        double s = 0.0;
        for (int m = 0; m < E; ++m) s += inv[m < b ? b - m : m - b];
        s0[b] = s;
    }
    for (int a = 0; a < 64; ++a) {
        for (int b = a; b <= 127 - a; ++b) {
            double g = 0.0;
            for (int m = 0; m < E; ++m)
                g += inv[m < a ? a - m : m - a] * inv[m < b ? b - m : m - b];
            float val = (float)(g - s0[a] * s0[b] / (double)(E - 1));
            t.v[a * E + b] = val;
            t.v[b * E + a] = val;
            t.v[(127 - a) * E + (127 - b)] = val;
            t.v[(127 - b) * E + (127 - a)] = val;
        }
    }
    return t;
}

__device__ const C0Table g_C0tab = make_c0();

__device__ __forceinline__ unsigned ld_acq(const unsigned* p) {
    unsigned v;
    asm volatile("ld.acquire.cta.u32 %0, [%1];" : "=r"(v) : "l"(p) : "memory");
    return v;
}

// ---------------------------------------------------------------------------
// Split-half pipelined kernel, coarse sync, ROLLED gather loops (predication
// of below-diagonal gathers must survive; unrolling lets the compiler hoist
// the guarded loads and re-add their bank traffic -- measured in R13).
//  sync A (keys staged)
//  round A: warps 0-15 rank f=0..15  ||  warps 16-31 load C0 (LDG latency)
//  sync B (f0-15 ranks + C0 ready)
//  round B: warps 16-31 rank f=16..31, fence + atomicAdd(cnt)
//           || warps 0-15 gather f=0..15 (barrier-guaranteed, no waits)
//  single spin on cnt==16, then remaining gathers.
// ---------------------------------------------------------------------------
__global__ __launch_bounds__(1024, 1)
void spearman_main_kernel(const float* __restrict__ de, float* __restrict__ out) {
    extern __shared__ char smem[];
    float*    C0s = (float*)   (smem + SMEM_C0);
    float*    ksf = (float*)   (smem + SMEM_KS);
    uint2*    cp  = (uint2*)   (smem + SMEM_CP);
    unsigned* rpq = (unsigned*)(smem + SMEM_RP);   // [f][w] uint2, stride 33
    unsigned* cnt = (unsigned*)(smem + SMEM_CNT);
    float*    T   = (float*)   (smem + SMEM_C0);   // reuse after phase 2

    const int t = threadIdx.x;
    const int b = blockIdx.x;
    const int w = t >> 5;
    const int l = t & 31;

    // ---- Stage keys (all threads) + zero counter
    {
        const float4* din4 = (const float4*)(de + (size_t)b * (E * F));
        float4 v = din4[t];                 // e = t/8, f = (t%8)*4 .. +3
        int e  = t >> 3;
        int f0 = (t & 7) << 2;
        ksf[(f0 + 0) * 132 + e] = v.x;
        ksf[(f0 + 1) * 132 + e] = v.y;
        ksf[(f0 + 2) * 132 + e] = v.z;
        ksf[(f0 + 3) * 132 + e] = v.w;
    }
    if (t == 0) *cnt = 0;
    __syncthreads();                        // sync A

    auto rank_f = [&](int fw) {
        const float* krow = ksf + fw * 132;
        float xe0 = krow[l];
        float xe1 = krow[l + 32];
        float xe2 = krow[l + 64];
        float xe3 = krow[l + 96];
        const float4* krow4 = (const float4*)krow;
        int c0 = 0, c1 = 0, c2 = 0, c3 = 0;
        #pragma unroll 8
        for (int m4 = 0; m4 < 32; ++m4) {
            float4 q = krow4[m4];
            c0 += (q.x < xe0) + (q.y < xe0) + (q.z < xe0) + (q.w < xe0);
            c1 += (q.x < xe1) + (q.y < xe1) + (q.z < xe1) + (q.w < xe1);
            c2 += (q.x < xe2) + (q.y < xe2) + (q.z < xe2) + (q.w < xe2);
            c3 += (q.x < xe3) + (q.y < xe3) + (q.z < xe3) + (q.w < xe3);
        }
        cp[fw * 32 + l] = make_uint2(((unsigned)c0 << 2) | ((unsigned)c1 << 18),
                                     ((unsigned)c2 << 2) | ((unsigned)c3 << 18));
        const unsigned full = 0xFFFFFFFFu;
        int e0s = (2 * l) & 31;
        int e1s = (2 * l + 1) & 31;
        bool hi = (l >= 16);
        int rA0 = __shfl_sync(full, c0, e0s);
        int rB0 = __shfl_sync(full, c1, e0s);
        int rA1 = __shfl_sync(full, c0, e1s);
        int rB1 = __shfl_sync(full, c1, e1s);
        unsigned word0 = ((unsigned)(hi ? rB0 : rA0) << 9)
                       | ((unsigned)(hi ? rB1 : rA1) << 25);
        int rC0 = __shfl_sync(full, c2, e0s);
        int rD0 = __shfl_sync(full, c3, e0s);
        int rC1 = __shfl_sync(full, c2, e1s);
        int rD1 = __shfl_sync(full, c3, e1s);
        unsigned word1 = ((unsigned)(hi ? rD0 : rC0) << 9)
                       | ((unsigned)(hi ? rD1 : rC1) << 25);
        rpq[(fw * 33 + l) * 2]            = word0;
        rpq[(fw * 33 + (31 - l)) * 2 + 1] = word1;
    };

    // ---- Round A: warps 0-15 rank; warps 16-31 load C0 table
    if (w < 16) {
        rank_f(w);
    } else {
        int u = t - 512;
        const float4* c4 = (const float4*)g_C0tab.v;
        float4* s4 = (float4*)C0s;
        #pragma unroll
        for (int i = 0; i < 8; ++i) s4[u + 512 * i] = c4[u + 512 * i];
    }
    __syncthreads();                        // sync B

    // ---- Round B: warps 16-31 rank f=w, publish via counter
    if (w >= 16) {
        rank_f(w);
        __syncwarp();
        if (l == 0) {
            __threadfence_block();          // release ranks before count
            atomicAdd(cnt, 1u);
        }
    }

    // ---- Phase 2: gather-accumulate (ROLLED loops; predication preserved)
    const int j0 = 2 * w, j1 = 2 * w + 1, j2 = 126 - 2 * w, j3 = 127 - 2 * w;
    const char* C0b = (const char*)C0s;

    if (w < 16) {
        float a0[4] = {0,0,0,0}, a1[4] = {0,0,0,0};
        float a2 = 0.0f, a3 = 0.0f;
        const bool p0  = (l >= j0);
        const bool p1  = (l >  j0);
        const bool p2  = (l >= 30 - j0);
        const bool p3  = (l >  30 - j0);
        auto gbody = [&](int f) {
            uint2 c = cp[f * 32 + l];
            uint2 rq = *(const uint2*)&rpq[(f * 33 + w) * 2];
            int ckb0 = c.x & 0xFFFF, ckb1 = c.x >> 16;
            int ckb2 = c.y & 0xFFFF, ckb3 = c.y >> 16;
            const char* R0 = C0b + (rq.x & 0xFFFF);
            const char* R1 = C0b + (rq.x >> 16);
            const char* R2 = C0b + (rq.y & 0xFFFF);
            const char* R3 = C0b + (rq.y >> 16);
            if (p0) a0[0] += *(const float*)(R0 + ckb0);
            a0[1] += *(const float*)(R0 + ckb1);
            a0[2] += *(const float*)(R0 + ckb2);
            a0[3] += *(const float*)(R0 + ckb3);
            if (p1) a1[0] += *(const float*)(R1 + ckb0);
            a1[1] += *(const float*)(R1 + ckb1);
            a1[2] += *(const float*)(R1 + ckb2);
            a1[3] += *(const float*)(R1 + ckb3);
            if (p2) a2 += *(const float*)(R2 + ckb3);
            if (p3) a3 += *(const float*)(R3 + ckb3);
        };
        #pragma unroll 1
        for (int f = 0; f < 16; ++f) gbody(f);             // barrier-guaranteed
        if (l == 0) { while (ld_acq(cnt) < 16u) {} }       // single event wait
        __syncwarp();
        #pragma unroll 1
        for (int f = 16; f < 32; ++f) gbody(f);
        __syncthreads();   // everyone done reading C0s/cp/rpq
        const float s = 1.0f / (float)F;
        #pragma unroll
        for (int m = 0; m < 4; ++m) {
            int k = (m << 5) + l;
            if (k >= j0) T[j0 * 129 + k] = a0[m] * s;
            if (k >= j1) T[j1 * 129 + k] = a1[m] * s;
        }
        { int k = 96 + l; if (k >= j2) T[j2 * 129 + k] = a2 * s;
                          if (k >= j3) T[j3 * 129 + k] = a3 * s; }
    } else {
        float a0[3] = {0,0,0}, a1[3] = {0,0,0};
        float a2[2] = {0,0},   a3[2] = {0,0};
        const bool p0 = (l >= j0 - 32);
        const bool p1 = (l >  j0 - 32);
        const bool p2 = (l >= j2 - 64);
        const bool p3 = (l >  j2 - 64);
        if (l == 0) { while (ld_acq(cnt) < 16u) {} }       // single event wait
        __syncwarp();
        #pragma unroll 1
        for (int f = 0; f < 32; ++f) {
            uint2 c = cp[f * 32 + l];
            uint2 rq = *(const uint2*)&rpq[(f * 33 + w) * 2];
            int ckb1 = c.x >> 16;
            int ckb2 = c.y & 0xFFFF, ckb3 = c.y >> 16;
            const char* R0 = C0b + (rq.x & 0xFFFF);
            const char* R1 = C0b + (rq.x >> 16);
            const char* R2 = C0b + (rq.y & 0xFFFF);
            const char* R3 = C0b + (rq.y >> 16);
            if (p0) a0[0] += *(const float*)(R0 + ckb1);
            a0[1] += *(const float*)(R0 + ckb2);
            a0[2] += *(const float*)(R0 + ckb3);
            if (p1) a1[0] += *(const float*)(R1 + ckb1);
            a1[1] += *(const float*)(R1 + ckb2);
            a1[2] += *(const float*)(R1 + ckb3);
            if (p2) a2[0] += *(const float*)(R2 + ckb2);
            a2[1] += *(const float*)(R2 + ckb3);
            if (p3) a3[0] += *(const float*)(R3 + ckb2);
            a3[1] += *(const float*)(R3 + ckb3);
        }
        __syncthreads();
        const float s = 1.0f / (float)F;
        #pragma unroll
        for (int m = 1; m < 4; ++m) {
            int k = (m << 5) + l;
            if (k >= j0) T[j0 * 129 + k] = a0[m - 1] * s;
            if (k >= j1) T[j1 * 129 + k] = a1[m - 1] * s;
        }
        #pragma unroll
        for (int m = 2; m < 4; ++m) {
            int k = (m << 5) + l;
            if (k >= j2) T[j2 * 129 + k] = a2[m - 2] * s;
            if (k >= j3) T[j3 * 129 + k] = a3[m - 2] * s;
        }
    }
    __syncthreads();

    // ---- Phase 3: mirrored writeout. Warp w -> rows 4w..4w+3, coalesced.
    float* o = out + (size_t)b * (E * E);
    #pragma unroll
    for (int jr = 0; jr < 4; ++jr) {
        int j = (w << 2) + jr;
        float* orow = o + j * E;
        #pragma unroll
        for (int m = 0; m < 4; ++m) {
            int k = (m << 5) + l;
            float v = (k >= j) ? T[j * 129 + k] : T[k * 129 + j];
            orow[k] = v;
        }
    }
}

extern "C" void kernel_launch(void* const* d_in, const int* in_sizes, int n_in,
                              void* d_out, int out_size) {
    const float* de = (const float*)d_in[0];
    float* out = (float*)d_out;
    int B = in_sizes[0] / (E * F);

    cudaFuncSetAttribute(spearman_main_kernel,
                         cudaFuncAttributeMaxDynamicSharedMemorySize, SMEM_TOTAL);

    spearman_main_kernel<<<B, 1024, SMEM_TOTAL>>>(de, out);
}

// round 15
// speedup vs baseline: 1.0021x; 1.0021x over previous
#include <cuda_runtime.h>
#include <cstdint>

#define E 128
#define F 32

// smem layout (dynamic, bytes):
//   C0s : 16384 floats      [0, 65536)
//   ksf : 32*132 floats     [65536, 82432)   (raw keys, transposed, stride 132)
//   cp  : 32*32 uint2       [82432, 90624)   (pre-scaled col byte offsets, 16b packed)
//   rpq : 32*33 uint2       [90624, 99072)   (row byte offsets, [f][w] = {pair_w, pair_63-w})
//   cnt : 1 u32             [99072, 99076)   (round-B ranks-done counter)
// After phase 2 the front region is reused as the staging tile
//   T   : 128*129 floats    [0, 66048)
#define SMEM_C0     0
#define SMEM_KS     65536
#define SMEM_CP     82432
#define SMEM_RP     90624
#define SMEM_CNT    99072
#define SMEM_TOTAL  99076

// ---------------------------------------------------------------------------
// Compile-time fixed table C0[a,b] = (W0^2)[a,b] - s0[a]*s0[b]/(E-1),
// W0[a,b] = 1/(|a-b|+1). Persymmetry quarters the constexpr work.
// ---------------------------------------------------------------------------
struct C0Table { float v[E * E]; };

static constexpr C0Table make_c0() {
    C0Table t{};
    double inv[E] = {};
    for (int i = 0; i < E; ++i) inv[i] = 1.0 / (double)(i + 1);
    double s0[E] = {};
    for (int b = 0; b < E; ++b) {
        double s = 0.0;
        for (int m = 0; m < E; ++m) s += inv[m < b ? b - m : m - b];
        s0[b] = s;
    }
    for (int a = 0; a < 64; ++a) {
        for (int b = a; b <= 127 - a; ++b) {
            double g = 0.0;
            for (int m = 0; m < E; ++m)
                g += inv[m < a ? a - m : m - a] * inv[m < b ? b - m : m - b];
            float val = (float)(g - s0[a] * s0[b] / (double)(E - 1));
            t.v[a * E + b] = val;
            t.v[b * E + a] = val;
            t.v[(127 - a) * E + (127 - b)] = val;
            t.v[(127 - b) * E + (127 - a)] = val;
        }
    }
    return t;
}

__device__ const C0Table g_C0tab = make_c0();

__device__ __forceinline__ unsigned ld_acq(const unsigned* p) {
    unsigned v;
    asm volatile("ld.acquire.cta.u32 %0, [%1];" : "=r"(v) : "l"(p) : "memory");
    return v;
}

// ---------------------------------------------------------------------------
// Split-half pipelined kernel. Coarse counter sync + own-f-first gathering:
//  sync A (keys staged)
//  round A: warps 0-15 rank f=0..15  ||  warps 16-31 load C0 (LDG latency)
//  sync B (f0-15 ranks + C0 ready)
//  round B: warps 16-31 rank f=16..31, fence + atomicAdd(cnt),
//             gather OWN f immediately (no wait), ONE spin, rotated peers,
//             then f0-15 straight.
//           || warps 0-15 gather f0-15 straight (no waits), ONE spin,
//             then f16-31 straight.
//  All gather loops ROLLED (unrolling hoists predicated below-diagonal
//  loads and re-adds their bank traffic -- measured R13).
// ---------------------------------------------------------------------------
__global__ __launch_bounds__(1024, 1)
void spearman_main_kernel(const float* __restrict__ de, float* __restrict__ out) {
    extern __shared__ char smem[];
    float*    C0s = (float*)   (smem + SMEM_C0);
    float*    ksf = (float*)   (smem + SMEM_KS);
    uint2*    cp  = (uint2*)   (smem + SMEM_CP);
    unsigned* rpq = (unsigned*)(smem + SMEM_RP);   // [f][w] uint2, stride 33
    unsigned* cnt = (unsigned*)(smem + SMEM_CNT);
    float*    T   = (float*)   (smem + SMEM_C0);   // reuse after phase 2

    const int t = threadIdx.x;
    const int b = blockIdx.x;
    const int w = t >> 5;
    const int l = t & 31;

    // ---- Stage keys (all threads) + zero counter
    {
        const float4* din4 = (const float4*)(de + (size_t)b * (E * F));
        float4 v = din4[t];                 // e = t/8, f = (t%8)*4 .. +3
        int e  = t >> 3;
        int f0 = (t & 7) << 2;
        ksf[(f0 + 0) * 132 + e] = v.x;
        ksf[(f0 + 1) * 132 + e] = v.y;
        ksf[(f0 + 2) * 132 + e] = v.z;
        ksf[(f0 + 3) * 132 + e] = v.w;
    }
    if (t == 0) *cnt = 0;
    __syncthreads();                        // sync A

    auto rank_f = [&](int fw) {
        const float* krow = ksf + fw * 132;
        float xe0 = krow[l];
        float xe1 = krow[l + 32];
        float xe2 = krow[l + 64];
        float xe3 = krow[l + 96];
        const float4* krow4 = (const float4*)krow;
        int c0 = 0, c1 = 0, c2 = 0, c3 = 0;
        #pragma unroll 8
        for (int m4 = 0; m4 < 32; ++m4) {
            float4 q = krow4[m4];
            c0 += (q.x < xe0) + (q.y < xe0) + (q.z < xe0) + (q.w < xe0);
            c1 += (q.x < xe1) + (q.y < xe1) + (q.z < xe1) + (q.w < xe1);
            c2 += (q.x < xe2) + (q.y < xe2) + (q.z < xe2) + (q.w < xe2);
            c3 += (q.x < xe3) + (q.y < xe3) + (q.z < xe3) + (q.w < xe3);
        }
        cp[fw * 32 + l] = make_uint2(((unsigned)c0 << 2) | ((unsigned)c1 << 18),
                                     ((unsigned)c2 << 2) | ((unsigned)c3 << 18));
        const unsigned full = 0xFFFFFFFFu;
        int e0s = (2 * l) & 31;
        int e1s = (2 * l + 1) & 31;
        bool hi = (l >= 16);
        int rA0 = __shfl_sync(full, c0, e0s);
        int rB0 = __shfl_sync(full, c1, e0s);
        int rA1 = __shfl_sync(full, c0, e1s);
        int rB1 = __shfl_sync(full, c1, e1s);
        unsigned word0 = ((unsigned)(hi ? rB0 : rA0) << 9)
                       | ((unsigned)(hi ? rB1 : rA1) << 25);
        int rC0 = __shfl_sync(full, c2, e0s);
        int rD0 = __shfl_sync(full, c3, e0s);
        int rC1 = __shfl_sync(full, c2, e1s);
        int rD1 = __shfl_sync(full, c3, e1s);
        unsigned word1 = ((unsigned)(hi ? rD0 : rC0) << 9)
                       | ((unsigned)(hi ? rD1 : rC1) << 25);
        rpq[(fw * 33 + l) * 2]            = word0;
        rpq[(fw * 33 + (31 - l)) * 2 + 1] = word1;
    };

    // ---- Round A: warps 0-15 rank; warps 16-31 load C0 table
    if (w < 16) {
        rank_f(w);
    } else {
        int u = t - 512;
        const float4* c4 = (const float4*)g_C0tab.v;
        float4* s4 = (float4*)C0s;
        #pragma unroll
        for (int i = 0; i < 8; ++i) s4[u + 512 * i] = c4[u + 512 * i];
    }
    __syncthreads();                        // sync B

    // ---- Round B: warps 16-31 rank f=w, publish via counter
    if (w >= 16) {
        rank_f(w);
        __syncwarp();
        if (l == 0) {
            __threadfence_block();          // release ranks before count
            atomicAdd(cnt, 1u);
        }
    }

    // ---- Phase 2: gather-accumulate (rolled loops; predication preserved)
    const int j0 = 2 * w, j1 = 2 * w + 1, j2 = 126 - 2 * w, j3 = 127 - 2 * w;
    const char* C0b = (const char*)C0s;

    if (w < 16) {
        float a0[4] = {0,0,0,0}, a1[4] = {0,0,0,0};
        float a2 = 0.0f, a3 = 0.0f;
        const bool p0  = (l >= j0);
        const bool p1  = (l >  j0);
        const bool p2  = (l >= 30 - j0);
        const bool p3  = (l >  30 - j0);
        auto gbody = [&](int f) {
            uint2 c = cp[f * 32 + l];
            uint2 rq = *(const uint2*)&rpq[(f * 33 + w) * 2];
            int ckb0 = c.x & 0xFFFF, ckb1 = c.x >> 16;
            int ckb2 = c.y & 0xFFFF, ckb3 = c.y >> 16;
            const char* R0 = C0b + (rq.x & 0xFFFF);
            const char* R1 = C0b + (rq.x >> 16);
            const char* R2 = C0b + (rq.y & 0xFFFF);
            const char* R3 = C0b + (rq.y >> 16);
            if (p0) a0[0] += *(const float*)(R0 + ckb0);
            a0[1] += *(const float*)(R0 + ckb1);
            a0[2] += *(const float*)(R0 + ckb2);
            a0[3] += *(const float*)(R0 + ckb3);
            if (p1) a1[0] += *(const float*)(R1 + ckb0);
            a1[1] += *(const float*)(R1 + ckb1);
            a1[2] += *(const float*)(R1 + ckb2);
            a1[3] += *(const float*)(R1 + ckb3);
            if (p2) a2 += *(const float*)(R2 + ckb3);
            if (p3) a3 += *(const float*)(R3 + ckb3);
        };
        #pragma unroll 1
        for (int f = 0; f < 16; ++f) gbody(f);             // barrier-guaranteed
        if (l == 0) { while (ld_acq(cnt) < 16u) {} }       // single event wait
        __syncwarp();
        #pragma unroll 1
        for (int f = 16; f < 32; ++f) gbody(f);
        __syncthreads();   // everyone done reading C0s/cp/rpq
        const float s = 1.0f / (float)F;
        #pragma unroll
        for (int m = 0; m < 4; ++m) {
            int k = (m << 5) + l;
            if (k >= j0) T[j0 * 129 + k] = a0[m] * s;
            if (k >= j1) T[j1 * 129 + k] = a1[m] * s;
        }
        { int k = 96 + l; if (k >= j2) T[j2 * 129 + k] = a2 * s;
                          if (k >= j3) T[j3 * 129 + k] = a3 * s; }
    } else {
        float a0[3] = {0,0,0}, a1[3] = {0,0,0};
        float a2[2] = {0,0},   a3[2] = {0,0};
        const bool p0 = (l >= j0 - 32);
        const bool p1 = (l >  j0 - 32);
        const bool p2 = (l >= j2 - 64);
        const bool p3 = (l >  j2 - 64);
        auto gbody = [&](int f) {
            uint2 c = cp[f * 32 + l];
            uint2 rq = *(const uint2*)&rpq[(f * 33 + w) * 2];
            int ckb1 = c.x >> 16;
            int ckb2 = c.y & 0xFFFF, ckb3 = c.y >> 16;
            const char* R0 = C0b + (rq.x & 0xFFFF);
            const char* R1 = C0b + (rq.x >> 16);
            const char* R2 = C0b + (rq.y & 0xFFFF);
            const char* R3 = C0b + (rq.y >> 16);
            if (p0) a0[0] += *(const float*)(R0 + ckb1);
            a0[1] += *(const float*)(R0 + ckb2);
            a0[2] += *(const float*)(R0 + ckb3);
            if (p1) a1[0] += *(const float*)(R1 + ckb1);
            a1[1] += *(const float*)(R1 + ckb2);
            a1[2] += *(const float*)(R1 + ckb3);
            if (p2) a2[0] += *(const float*)(R2 + ckb2);
            a2[1] += *(const float*)(R2 + ckb3);
            if (p3) a3[0] += *(const float*)(R3 + ckb2);
            a3[1] += *(const float*)(R3 + ckb3);
        };
        gbody(w);                                          // OWN f: no wait
        if (l == 0) { while (ld_acq(cnt) < 16u) {} }       // single event wait
        __syncwarp();
        #pragma unroll 1
        for (int i = 1; i < 16; ++i) gbody(16 + ((w + i) & 15));  // peers
        #pragma unroll 1
        for (int f = 0; f < 16; ++f) gbody(f);             // barrier-guaranteed
        __syncthreads();
        const float s = 1.0f / (float)F;
        #pragma unroll
        for (int m = 1; m < 4; ++m) {
            int k = (m << 5) + l;
            if (k >= j0) T[j0 * 129 + k] = a0[m - 1] * s;
            if (k >= j1) T[j1 * 129 + k] = a1[m - 1] * s;
        }
        #pragma unroll
        for (int m = 2; m < 4; ++m) {
            int k = (m << 5) + l;
            if (k >= j2) T[j2 * 129 + k] = a2[m - 2] * s;
            if (k >= j3) T[j3 * 129 + k] = a3[m - 2] * s;
        }
    }
    __syncthreads();

    // ---- Phase 3: mirrored writeout. Warp w -> rows 4w..4w+3, coalesced.
    float* o = out + (size_t)b * (E * E);
    #pragma unroll
    for (int jr = 0; jr < 4; ++jr) {
        int j = (w << 2) + jr;
        float* orow = o + j * E;
        #pragma unroll
        for (int m = 0; m < 4; ++m) {
            int k = (m << 5) + l;
            float v = (k >= j) ? T[j * 129 + k] : T[k * 129 + j];
            orow[k] = v;
        }
    }
}

extern "C" void kernel_launch(void* const* d_in, const int* in_sizes, int n_in,
                              void* d_out, int out_size) {
    const float* de = (const float*)d_in[0];
    float* out = (float*)d_out;
    int B = in_sizes[0] / (E * F);

    cudaFuncSetAttribute(spearman_main_kernel,
                         cudaFuncAttributeMaxDynamicSharedMemorySize, SMEM_TOTAL);

    spearman_main_kernel<<<B, 1024, SMEM_TOTAL>>>(de, out);
}

// round 16
// speedup vs baseline: 1.0115x; 1.0094x over previous
#include <cuda_runtime.h>
#include <cstdint>

#define E 128
#define F 32

// smem layout (dynamic, bytes):
//   C0s   : 16384 floats      [0, 65536)
//   ksf   : 32*132 floats     [65536, 82432)   (raw keys, transposed, stride 132)
//   cp    : 32*32 uint2       [82432, 90624)   (pre-scaled col byte offsets, 16b packed)
//   rpq   : 32*33 uint2       [90624, 99072)   (row byte offsets, [f][w] = {pair_w, pair_63-w})
//   flags : 32 u32            [99072, 99200)   (per-f rank-ready flags; only f>=16 used)
// After phase 2 the front region is reused as the staging tile
//   T     : 128*129 floats    [0, 66048)
#define SMEM_C0     0
#define SMEM_KS     65536
#define SMEM_CP     82432
#define SMEM_RP     90624
#define SMEM_FL     99072
#define SMEM_TOTAL  99200

// ---------------------------------------------------------------------------
// Compile-time fixed table C0[a,b] = (W0^2)[a,b] - s0[a]*s0[b]/(E-1),
// W0[a,b] = 1/(|a-b|+1). Persymmetry quarters the constexpr work.
// ---------------------------------------------------------------------------
struct C0Table { float v[E * E]; };

static constexpr C0Table make_c0() {
    C0Table t{};
    double inv[E] = {};
    for (int i = 0; i < E; ++i) inv[i] = 1.0 / (double)(i + 1);
    double s0[E] = {};
    for (int b = 0; b < E; ++b) {
        double s = 0.0;
        for (int m = 0; m < E; ++m) s += inv[m < b ? b - m : m - b];
        s0[b] = s;
    }
    for (int a = 0; a < 64; ++a) {
        for (int b = a; b <= 127 - a; ++b) {
            double g = 0.0;
            for (int m = 0; m < E; ++m)
                g += inv[m < a ? a - m : m - a] * inv[m < b ? b - m : m - b];
            float val = (float)(g - s0[a] * s0[b] / (double)(E - 1));
            t.v[a * E + b] = val;
            t.v[b * E + a] = val;
            t.v[(127 - a) * E + (127 - b)] = val;
            t.v[(127 - b) * E + (127 - a)] = val;
        }
    }
    return t;
}

__device__ const C0Table g_C0tab = make_c0();

__device__ __forceinline__ unsigned ld_acq(const unsigned* p) {
    unsigned v;
    asm volatile("ld.acquire.cta.u32 %0, [%1];" : "=r"(v) : "l"(p) : "memory");
    return v;
}
__device__ __forceinline__ void st_rel(unsigned* p, unsigned v) {
    asm volatile("st.release.cta.u32 [%0], %1;" :: "l"(p), "r"(v) : "memory");
}

// ---------------------------------------------------------------------------
// Split-half pipelined kernel -- R12 sync design (measured best) + cleanups:
//  sync A (keys staged)
//  round A: warps 0-15 rank f=0..15  ||  warps 16-31 load C0 (LDG latency)
//  sync B (f0-15 ranks + C0 ready)
//  round B: warps 16-31 rank f=16..31, release per-f flag
//           || warps 0-15 gather f0-15 straight (barrier-guaranteed)
//  cross-half consumption: per-f flag ACQUIRE, rotated by w (pipelines the
//  round-B tail -- a single coarse counter gates on the slowest warp and
//  measured 0.4-0.9us worse in R14/R15).
//  All gather loops pinned ROLLED: unrolling hoists the predicated
//  below-diagonal loads and re-adds their bank traffic (measured R13).
// ---------------------------------------------------------------------------
__global__ __launch_bounds__(1024, 1)
void spearman_main_kernel(const float* __restrict__ de, float* __restrict__ out) {
    extern __shared__ char smem[];
    float*    C0s   = (float*)   (smem + SMEM_C0);
    float*    ksf   = (float*)   (smem + SMEM_KS);
    uint2*    cp    = (uint2*)   (smem + SMEM_CP);
    unsigned* rpq   = (unsigned*)(smem + SMEM_RP);   // [f][w] uint2, stride 33
    unsigned* flags = (unsigned*)(smem + SMEM_FL);
    float*    T     = (float*)   (smem + SMEM_C0);   // reuse after phase 2

    const int t = threadIdx.x;
    const int b = blockIdx.x;
    const int w = t >> 5;
    const int l = t & 31;

    // ---- Stage keys (all threads) + zero flags
    {
        const float4* din4 = (const float4*)(de + (size_t)b * (E * F));
        float4 v = din4[t];                 // e = t/8, f = (t%8)*4 .. +3
        int e  = t >> 3;
        int f0 = (t & 7) << 2;
        ksf[(f0 + 0) * 132 + e] = v.x;
        ksf[(f0 + 1) * 132 + e] = v.y;
        ksf[(f0 + 2) * 132 + e] = v.z;
        ksf[(f0 + 3) * 132 + e] = v.w;
    }
    if (t < F) flags[t] = 0;
    __syncthreads();                        // sync A

    auto rank_f = [&](int fw) {
        const float* krow = ksf + fw * 132;
        float xe0 = krow[l];
        float xe1 = krow[l + 32];
        float xe2 = krow[l + 64];
        float xe3 = krow[l + 96];
        const float4* krow4 = (const float4*)krow;
        int c0 = 0, c1 = 0, c2 = 0, c3 = 0;
        #pragma unroll 8
        for (int m4 = 0; m4 < 32; ++m4) {
            float4 q = krow4[m4];
            c0 += (q.x < xe0) + (q.y < xe0) + (q.z < xe0) + (q.w < xe0);
            c1 += (q.x < xe1) + (q.y < xe1) + (q.z < xe1) + (q.w < xe1);
            c2 += (q.x < xe2) + (q.y < xe2) + (q.z < xe2) + (q.w < xe2);
            c3 += (q.x < xe3) + (q.y < xe3) + (q.z < xe3) + (q.w < xe3);
        }
        cp[fw * 32 + l] = make_uint2(((unsigned)c0 << 2) | ((unsigned)c1 << 18),
                                     ((unsigned)c2 << 2) | ((unsigned)c3 << 18));
        const unsigned full = 0xFFFFFFFFu;
        int e0s = (2 * l) & 31;
        int e1s = (2 * l + 1) & 31;
        bool hi = (l >= 16);
        int rA0 = __shfl_sync(full, c0, e0s);
        int rB0 = __shfl_sync(full, c1, e0s);
        int rA1 = __shfl_sync(full, c0, e1s);
        int rB1 = __shfl_sync(full, c1, e1s);
        unsigned word0 = ((unsigned)(hi ? rB0 : rA0) << 9)
                       | ((unsigned)(hi ? rB1 : rA1) << 25);
        int rC0 = __shfl_sync(full, c2, e0s);
        int rD0 = __shfl_sync(full, c3, e0s);
        int rC1 = __shfl_sync(full, c2, e1s);
        int rD1 = __shfl_sync(full, c3, e1s);
        unsigned word1 = ((unsigned)(hi ? rD0 : rC0) << 9)
                       | ((unsigned)(hi ? rD1 : rC1) << 25);
        rpq[(fw * 33 + l) * 2]            = word0;
        rpq[(fw * 33 + (31 - l)) * 2 + 1] = word1;
    };

    // ---- Round A: warps 0-15 rank; warps 16-31 load C0 table
    if (w < 16) {
        rank_f(w);
    } else {
        int u = t - 512;
        const float4* c4 = (const float4*)g_C0tab.v;
        float4* s4 = (float4*)C0s;
        #pragma unroll
        for (int i = 0; i < 8; ++i) s4[u + 512 * i] = c4[u + 512 * i];
    }
    __syncthreads();                        // sync B

    // ---- Round B: warps 16-31 rank f=w, release per-f flag
    if (w >= 16) {
        rank_f(w);
        __syncwarp();
        if (l == 0) st_rel(&flags[w], 1u);
    }

    // ---- Phase 2: gather-accumulate (rolled loops; predication preserved)
    const int j0 = 2 * w, j1 = 2 * w + 1, j2 = 126 - 2 * w, j3 = 127 - 2 * w;
    const char* C0b = (const char*)C0s;

    if (w < 16) {
        float a0[4] = {0,0,0,0}, a1[4] = {0,0,0,0};
        float a2 = 0.0f, a3 = 0.0f;
        const bool p0  = (l >= j0);
        const bool p1  = (l >  j0);
        const bool p2  = (l >= 30 - j0);
        const bool p3  = (l >  30 - j0);
        auto gbody = [&](int f) {
            uint2 c = cp[f * 32 + l];
            uint2 rq = *(const uint2*)&rpq[(f * 33 + w) * 2];
            int ckb0 = c.x & 0xFFFF, ckb1 = c.x >> 16;
            int ckb2 = c.y & 0xFFFF, ckb3 = c.y >> 16;
            const char* R0 = C0b + (rq.x & 0xFFFF);
            const char* R1 = C0b + (rq.x >> 16);
            const char* R2 = C0b + (rq.y & 0xFFFF);
            const char* R3 = C0b + (rq.y >> 16);
            if (p0) a0[0] += *(const float*)(R0 + ckb0);
            a0[1] += *(const float*)(R0 + ckb1);
            a0[2] += *(const float*)(R0 + ckb2);
            a0[3] += *(const float*)(R0 + ckb3);
            if (p1) a1[0] += *(const float*)(R1 + ckb0);
            a1[1] += *(const float*)(R1 + ckb1);
            a1[2] += *(const float*)(R1 + ckb2);
            a1[3] += *(const float*)(R1 + ckb3);
            if (p2) a2 += *(const float*)(R2 + ckb3);
            if (p3) a3 += *(const float*)(R3 + ckb3);
        };
        #pragma unroll 1
        for (int f = 0; f < 16; ++f) gbody(f);             // barrier-guaranteed
        #pragma unroll 1
        for (int i = 0; i < 16; ++i) {                     // flag-pipelined
            int f = 16 + ((w + i) & 15);
            if (l == 0) { while (ld_acq(&flags[f]) == 0) {} }
            __syncwarp();
            gbody(f);
        }
        __syncthreads();   // everyone done reading C0s/cp/rpq
        const float s = 1.0f / (float)F;
        #pragma unroll
        for (int m = 0; m < 4; ++m) {
            int k = (m << 5) + l;
            if (k >= j0) T[j0 * 129 + k] = a0[m] * s;
            if (k >= j1) T[j1 * 129 + k] = a1[m] * s;
        }
        { int k = 96 + l; if (k >= j2) T[j2 * 129 + k] = a2 * s;
                          if (k >= j3) T[j3 * 129 + k] = a3 * s; }
    } else {
        float a0[3] = {0,0,0}, a1[3] = {0,0,0};
        float a2[2] = {0,0},   a3[2] = {0,0};
        const bool p0 = (l >= j0 - 32);
        const bool p1 = (l >  j0 - 32);
        const bool p2 = (l >= j2 - 64);
        const bool p3 = (l >  j2 - 64);
        auto gbody = [&](int f) {
            uint2 c = cp[f * 32 + l];
            uint2 rq = *(const uint2*)&rpq[(f * 33 + w) * 2];
            int ckb1 = c.x >> 16;
            int ckb2 = c.y & 0xFFFF, ckb3 = c.y >> 16;
            const char* R0 = C0b + (rq.x & 0xFFFF);
            const char* R1 = C0b + (rq.x >> 16);
            const char* R2 = C0b + (rq.y & 0xFFFF);
            const char* R3 = C0b + (rq.y >> 16);
            if (p0) a0[0] += *(const float*)(R0 + ckb1);
            a0[1] += *(const float*)(R0 + ckb2);
            a0[2] += *(const float*)(R0 + ckb3);
            if (p1) a1[0] += *(const float*)(R1 + ckb1);
            a1[1] += *(const float*)(R1 + ckb2);
            a1[2] += *(const float*)(R1 + ckb3);
            if (p2) a2[0] += *(const float*)(R2 + ckb2);
            a2[1] += *(const float*)(R2 + ckb3);
            if (p3) a3[0] += *(const float*)(R3 + ckb2);
            a3[1] += *(const float*)(R3 + ckb3);
        };
        gbody(w);                                          // OWN f: no wait
        #pragma unroll 1
        for (int i = 1; i < 16; ++i) {                     // flag-pipelined peers
            int f = 16 + ((w + i) & 15);
            if (l == 0) { while (ld_acq(&flags[f]) == 0) {} }
            __syncwarp();
            gbody(f);
        }
        #pragma unroll 1
        for (int f = 0; f < 16; ++f) gbody(f);             // barrier-guaranteed
        __syncthreads();
        const float s = 1.0f / (float)F;
        #pragma unroll
        for (int m = 1; m < 4; ++m) {
            int k = (m << 5) + l;
            if (k >= j0) T[j0 * 129 + k] = a0[m - 1] * s;
            if (k >= j1) T[j1 * 129 + k] = a1[m - 1] * s;
        }
        #pragma unroll
        for (int m = 2; m < 4; ++m) {
            int k = (m << 5) + l;
            if (k >= j2) T[j2 * 129 + k] = a2[m - 2] * s;
            if (k >= j3) T[j3 * 129 + k] = a3[m - 2] * s;
        }
    }
    __syncthreads();

    // ---- Phase 3: mirrored writeout. Warp w -> rows 4w..4w+3, coalesced.
    float* o = out + (size_t)b * (E * E);
    #pragma unroll
    for (int jr = 0; jr < 4; ++jr) {
        int j = (w << 2) + jr;
        float* orow = o + j * E;
        #pragma unroll
        for (int m = 0; m < 4; ++m) {
            int k = (m << 5) + l;
            float v = (k >= j) ? T[j * 129 + k] : T[k * 129 + j];
            orow[k] = v;
        }
    }
}

extern "C" void kernel_launch(void* const* d_in, const int* in_sizes, int n_in,
                              void* d_out, int out_size) {
    const float* de = (const float*)d_in[0];
    float* out = (float*)d_out;
    int B = in_sizes[0] / (E * F);

    cudaFuncSetAttribute(spearman_main_kernel,
                         cudaFuncAttributeMaxDynamicSharedMemorySize, SMEM_TOTAL);

    spearman_main_kernel<<<B, 1024, SMEM_TOTAL>>>(de, out);
}